// round 4
// baseline (speedup 1.0000x reference)
#include <cuda_runtime.h>

// (B,C,D,H,W) = (4,8,16,256,256), k=3, stride=1, pad=1
#define BC   32
#define DD   16
#define HH   256
#define WW   256
#define HW   (HH*WW)
#define CHV  (DD*HW)

#define TH    8               // tile height
#define TXN   32              // threads in x
#define TWPIX 64              // tile width in pixels (2 px / thread)
#define ROWS  (TH+2)          // 10
#define COLS  (TWPIX+2)       // 66
#define TS    (ROWS*COLS)     // 660
#define NT    (TH*TXN)        // 256

__global__ void __launch_bounds__(NT, 4)
softargmax_kernel(const float* __restrict__ x, float* __restrict__ out)
{
    const int bc = blockIdx.z;
    const int h0 = blockIdx.y * TH;
    const int w0 = blockIdx.x * TWPIX;
    const int tid = threadIdx.x;
    const int tx = tid & 31;
    const int ty = tid >> 5;

    // double-buffered (e, e*x) slice tiles
    __shared__ __align__(16) float2 tile[2][TS];

    const float* __restrict__ xc = x + (size_t)bc * CHV;

    // slice-invariant halo load slots (3 slots cover TS=660 <= 3*256)
    int  off[3];
    bool inr[3], pred[3];
    #pragma unroll
    for (int j = 0; j < 3; j++) {
        int i = tid + j * NT;
        int r = i / COLS, c = i % COLS;
        int hh = h0 + r - 1, ww = w0 + c - 1;
        inr[j]  = (i < TS);
        pred[j] = inr[j] && (hh >= 0) && (hh < HH) && (ww >= 0) && (ww < WW);
        off[j]  = pred[j] ? hh * WW + ww : 0;
    }

    float rv[3];
    #pragma unroll
    for (int j = 0; j < 3; j++) rv[j] = pred[j] ? __ldg(xc + off[j]) : 0.f;

    #define PUBLISH(BUF)                                                     \
        _Pragma("unroll")                                                    \
        for (int j = 0; j < 3; j++) {                                        \
            if (inr[j]) {                                                    \
                float e = pred[j] ? __expf(rv[j]) : 0.f;                     \
                tile[BUF][tid + j * NT] = make_float2(e, e * rv[j]);         \
            }                                                                \
        }

    // s[0..3]={sum,xnum,ynum,vnum} px0 ; s[4..7] px1
    #define ACCUM(s, BUF)                                                    \
        _Pragma("unroll")                                                    \
        for (int r = 0; r < 3; r++) {                                        \
            const float4 A = *reinterpret_cast<const float4*>(               \
                &tile[BUF][(ty + r) * COLS + 2 * tx]);                       \
            const float4 B = *reinterpret_cast<const float4*>(               \
                &tile[BUF][(ty + r) * COLS + 2 * tx + 2]);                   \
            float rs0 = A.x + A.z + B.x;                                     \
            float rs1 = A.z + B.x + B.z;                                     \
            (s)[0] += rs0;          (s)[4] += rs1;                           \
            (s)[1] += B.x - A.x;    (s)[5] += B.z - A.z;                     \
            if (r == 0) { (s)[2] -= rs0; (s)[6] -= rs1; }                    \
            if (r == 2) { (s)[2] += rs0; (s)[6] += rs1; }                    \
            (s)[3] += A.y + A.w + B.y;                                       \
            (s)[7] += A.w + B.y + B.w;                                       \
        }

    float p[8], c[8], n[8];
    #pragma unroll
    for (int k = 0; k < 8; k++) { p[k] = 0.f; c[k] = 0.f; }

    // prologue: slice 0 -> buf0
    PUBLISH(0);
    #pragma unroll
    for (int j = 0; j < 3; j++) rv[j] = pred[j] ? __ldg(xc + HW + off[j]) : 0.f;
    __syncthreads();
    ACCUM(c, 0);

    const int h = h0 + ty;
    const int w = w0 + 2 * tx;
    float* __restrict__ coords = out + (size_t)bc * 3 * CHV;
    float* __restrict__ vals   = out + (size_t)BC * 3 * CHV + (size_t)bc * CHV;
    const size_t pixbase = (size_t)h * WW + w;

    #pragma unroll 4
    for (int d = 0; d < DD; d++) {
        #pragma unroll
        for (int k = 0; k < 8; k++) n[k] = 0.f;

        if (d + 1 < DD) {
            const int buf = (d + 1) & 1;
            PUBLISH(buf);                       // slice d+1
            if (d + 2 < DD) {                   // prefetch slice d+2
                const float* xs2 = xc + (size_t)(d + 2) * HW;
                #pragma unroll
                for (int j = 0; j < 3; j++)
                    rv[j] = pred[j] ? __ldg(xs2 + off[j]) : 0.f;
            }
            __syncthreads();                    // single barrier per slice
            ACCUM(n, buf);
        }

        const float inv0 = __fdividef(1.0f, p[0] + c[0] + n[0] + 1e-8f);
        const float inv1 = __fdividef(1.0f, p[4] + c[4] + n[4] + 1e-8f);
        const size_t base = (size_t)d * HW + pixbase;

        float2 z2 = make_float2((float)d + (n[0] - p[0]) * inv0,
                                (float)d + (n[4] - p[4]) * inv1);
        float2 x2 = make_float2((float)w       + (p[1] + c[1] + n[1]) * inv0,
                                (float)(w + 1) + (p[5] + c[5] + n[5]) * inv1);
        float2 y2 = make_float2((float)h + (p[2] + c[2] + n[2]) * inv0,
                                (float)h + (p[6] + c[6] + n[6]) * inv1);
        float2 v2 = make_float2((p[3] + c[3] + n[3]) * inv0,
                                (p[7] + c[7] + n[7]) * inv1);

        __stcs(reinterpret_cast<float2*>(coords + base), z2);
        __stcs(reinterpret_cast<float2*>(coords + (size_t)CHV + base), x2);
        __stcs(reinterpret_cast<float2*>(coords + 2 * (size_t)CHV + base), y2);
        __stcs(reinterpret_cast<float2*>(vals + base), v2);

        #pragma unroll
        for (int k = 0; k < 8; k++) { p[k] = c[k]; c[k] = n[k]; }
    }
}

extern "C" void kernel_launch(void* const* d_in, const int* in_sizes, int n_in,
                              void* d_out, int out_size) {
    const float* x = (const float*)d_in[0];
    float* out = (float*)d_out;
    softargmax_kernel<<<dim3(WW / TWPIX, HH / TH, BC), NT>>>(x, out);
}